// round 11
// baseline (speedup 1.0000x reference)
#include <cuda_runtime.h>
#include <cstdint>

#define NV 50000
#define NE 1600000

// ---------------- scratch ----------------
__device__ __align__(16) float g_A[NV * 512];        // [x | sage | gcn | gat] layer1 GEMM input
__device__ __align__(16) float g_H[NV * 128];        // layer1 output (pre-BN)
__device__ __align__(16) float g_P2[NV * 160];       // layer2 GEMM output [self|sage|gcn|gat]
__device__ __align__(16) uint32_t g_W1t[128 * 512];  // tf32, [n][k]
__device__ __align__(16) uint32_t g_W2t[160 * 128];  // tf32, [n][k]
__device__ float g_bias1[128];
__device__ int g_indeg[NV];
__device__ int g_outdeg[NV];
__device__ int g_rowofs[NV + 1];
__device__ int g_srcs[NE];
__device__ float g_ns[NV], g_nd[NV], g_invd[NV];
__device__ float g_el1[NV], g_er1[NV], g_el2[NV], g_er2[NV];
__device__ float g_wl1[128], g_wr1[128];
__device__ float g_bnsum[128], g_bnsq[128], g_bnsc[128], g_bnsh[128];
__device__ float g_w1[3], g_w2[3];

// ---------------- helpers ----------------
__device__ __forceinline__ float lrelu(float x) { return x > 0.f ? x : 0.2f * x; }
__device__ __forceinline__ float warp_max(float v) {
    #pragma unroll
    for (int o = 16; o; o >>= 1) v = fmaxf(v, __shfl_xor_sync(0xffffffffu, v, o));
    return v;
}
__device__ __forceinline__ float warp_sum(float v) {
    #pragma unroll
    for (int o = 16; o; o >>= 1) v += __shfl_xor_sync(0xffffffffu, v, o);
    return v;
}
__device__ __forceinline__ float4 shfl4(float4 v, int src) {
    float4 r;
    r.x = __shfl_sync(0xffffffffu, v.x, src);
    r.y = __shfl_sync(0xffffffffu, v.y, src);
    r.z = __shfl_sync(0xffffffffu, v.z, src);
    r.w = __shfl_sync(0xffffffffu, v.w, src);
    return r;
}
__device__ __forceinline__ uint32_t f2tf32(float v) {
    uint32_t r;
    asm("cvt.rna.tf32.f32 %0, %1;" : "=r"(r) : "f"(v));
    return r;
}
__device__ __forceinline__ void mma_tf32(float c[4], const uint32_t a[4], const uint32_t b[2]) {
    asm volatile(
        "mma.sync.aligned.m16n8k8.row.col.f32.tf32.tf32.f32 "
        "{%0,%1,%2,%3}, {%4,%5,%6,%7}, {%8,%9}, {%0,%1,%2,%3};"
        : "+f"(c[0]), "+f"(c[1]), "+f"(c[2]), "+f"(c[3])
        : "r"(a[0]), "r"(a[1]), "r"(a[2]), "r"(a[3]), "r"(b[0]), "r"(b[1]));
}

// ---------------- setup ----------------
__global__ void k_zero(const float* __restrict__ cw1, const float* __restrict__ cw2) {
    int i = blockIdx.x * blockDim.x + threadIdx.x;
    if (i < NV) { g_indeg[i] = 0; g_outdeg[i] = 0; }
    if (i < 128) { g_bnsum[i] = 0.f; g_bnsq[i] = 0.f; }
    if (i == 0) {
        float s1 = cw1[0] + cw1[1] + cw1[2];
        g_w1[0] = cw1[0] / s1; g_w1[1] = cw1[1] / s1; g_w1[2] = cw1[2] / s1;
        float s2 = cw2[0] + cw2[1] + cw2[2];
        g_w2[0] = cw2[0] / s2; g_w2[1] = cw2[1] / s2; g_w2[2] = cw2[2] / s2;
    }
}

__global__ void k_deg(const int* __restrict__ src, const int* __restrict__ dst) {
    int i = blockIdx.x * blockDim.x + threadIdx.x;
    if (i < NE) {
        atomicAdd(&g_indeg[dst[i]], 1);
        atomicAdd(&g_outdeg[src[i]], 1);
    }
}

// single-pass scan + node factors (rebuilds g_rowofs every replay)
__global__ void k_scan() {
    int t = threadIdx.x;
    const int CH = (NV + 1023) / 1024;
    int b0 = t * CH;
    int b1 = min(b0 + CH, NV);
    int sum = 0;
    for (int i = b0; i < b1; i++) sum += g_indeg[i];
    __shared__ int wsum[32];
    int lane = t & 31, wid = t >> 5;
    int v = sum;
    #pragma unroll
    for (int o = 1; o < 32; o <<= 1) {
        int u = __shfl_up_sync(0xffffffffu, v, o);
        if (lane >= o) v += u;
    }
    if (lane == 31) wsum[wid] = v;
    __syncthreads();
    if (wid == 0) {
        int wv = wsum[lane];
        #pragma unroll
        for (int o = 1; o < 32; o <<= 1) {
            int u = __shfl_up_sync(0xffffffffu, wv, o);
            if (lane >= o) wv += u;
        }
        wsum[lane] = wv;
    }
    __syncthreads();
    int excl = v - sum + (wid > 0 ? wsum[wid - 1] : 0);
    int run = excl;
    for (int i = b0; i < b1; i++) { g_rowofs[i] = run; run += g_indeg[i]; }
    if (t == 1023) g_rowofs[NV] = run;
    for (int i = b0; i < b1; i++) {
        float di = fmaxf((float)g_indeg[i], 1.f);
        float doo = fmaxf((float)g_outdeg[i], 1.f);
        g_nd[i] = rsqrtf(di);
        g_ns[i] = rsqrtf(doo);
        g_invd[i] = 1.f / di;
    }
}

// scatter with in-place cursor: afterwards g_rowofs[d] == old rowofs[d+1],
// so node w's range is [rowofs[w-1], rowofs[w]) (with rowofs[-1] := 0)
__global__ void k_scatter(const int* __restrict__ src, const int* __restrict__ dst) {
    int i = blockIdx.x * blockDim.x + threadIdx.x;
    if (i < NE) {
        int d = dst[i];
        int pos = atomicAdd(&g_rowofs[d], 1);
        g_srcs[pos] = src[i];
    }
}

// merged weight prep: W1t (scaled tf32 [n][k]), W2t, bias1, attention vectors
__global__ void k_wprep(const float* __restrict__ w11s, const float* __restrict__ w11n,
                        const float* __restrict__ w12, const float* __restrict__ w13,
                        const float* __restrict__ b11, const float* __restrict__ b12,
                        const float* __restrict__ b13,
                        const float* __restrict__ w21s, const float* __restrict__ w21n,
                        const float* __restrict__ w22, const float* __restrict__ w23,
                        const float* __restrict__ a13l, const float* __restrict__ a13r) {
    int i = blockIdx.x * blockDim.x + threadIdx.x;
    if (i < 128 * 512) {                      // W1t: c = n (0..127), k = 0..511
        int c = i >> 9, k = i & 511;
        float v;
        if (k < 128)      v = g_w1[0] * w11s[k * 128 + c];
        else if (k < 256) v = g_w1[0] * w11n[(k - 128) * 128 + c];
        else if (k < 384) v = g_w1[1] * w12[(k - 256) * 128 + c];
        else              v = g_w1[2] * w13[(k - 384) * 128 + c];
        g_W1t[i] = f2tf32(v);
    } else if (i < 65536 + 20480) {           // W2t: c = n (0..159), k = 0..127
        int j = i - 65536;
        int c = j >> 7, k = j & 127;
        float v;
        if (c < 40)       v = w21s[k * 40 + c];
        else if (c < 80)  v = w21n[k * 40 + (c - 40)];
        else if (c < 120) v = w22[k * 40 + (c - 80)];
        else              v = w23[k * 40 + (c - 120)];
        g_W2t[j] = f2tf32(v);
    } else if (i < 65536 + 20480 + 128) {     // attention vectors
        int k = i - (65536 + 20480);
        float sl = 0.f, sr = 0.f;
        for (int j = 0; j < 128; j++) {
            float w = w13[k * 128 + j];
            sl = fmaf(w, a13l[j], sl);
            sr = fmaf(w, a13r[j], sr);
        }
        g_wl1[k] = sl;
        g_wr1[k] = sr;
    }
    if (i < 128)
        g_bias1[i] = g_w1[0] * b11[i] + g_w1[1] * b12[i] + g_w1[2] * b13[i];
}

// per-node attention scalars for layer 1
__global__ void k_eler1(const float* __restrict__ x) {
    int w = (blockIdx.x * blockDim.x + threadIdx.x) >> 5;
    if (w >= NV) return;
    int lane = threadIdx.x & 31;
    float4 u = ((const float4*)(x + (size_t)w * 128))[lane];
    float4 wl = ((const float4*)g_wl1)[lane];
    float4 wr = ((const float4*)g_wr1)[lane];
    float el = u.x * wl.x + u.y * wl.y + u.z * wl.z + u.w * wl.w;
    float er = u.x * wr.x + u.y * wr.y + u.z * wr.z + u.w * wr.w;
    el = warp_sum(el);
    er = warp_sum(er);
    if (lane == 0) { g_el1[w] = el; g_er1[w] = er; }
}

// layer-1 edge pass: gather x[src], 4-edge unrolled (R4 form; shifted rowofs)
__global__ void k_edge1(const float* __restrict__ x) {
    int w = (blockIdx.x * blockDim.x + threadIdx.x) >> 5;
    if (w >= NV) return;
    int lane = threadIdx.x & 31;
    int s = (w > 0) ? g_rowofs[w - 1] : 0;
    int e = g_rowofs[w];
    float erv = g_er1[w];
    float mx = -1e30f;
    for (int j = s + lane; j < e; j += 32) mx = fmaxf(mx, g_el1[g_srcs[j]]);
    mx = warp_max(mx);
    float me = lrelu(mx + erv);

    float4 fs = make_float4(0, 0, 0, 0), fg = fs, fa = fs;
    float ss = 0.f;
    for (int base = s; base < e; base += 32) {
        int j = base + lane;
        int sj = 0;
        float aw = 0.f, nsv = 0.f;
        if (j < e) {
            sj = g_srcs[j];
            aw = __expf(lrelu(g_el1[sj] + erv) - me);
            nsv = g_ns[sj];
            ss += aw;
        }
        int cnt = min(32, e - base);
        int t = 0;
        for (; t + 4 <= cnt; t += 4) {
            int s0 = __shfl_sync(0xffffffffu, sj, t);
            int s1 = __shfl_sync(0xffffffffu, sj, t + 1);
            int s2 = __shfl_sync(0xffffffffu, sj, t + 2);
            int s3 = __shfl_sync(0xffffffffu, sj, t + 3);
            float A0 = __shfl_sync(0xffffffffu, aw, t);
            float A1 = __shfl_sync(0xffffffffu, aw, t + 1);
            float A2 = __shfl_sync(0xffffffffu, aw, t + 2);
            float A3 = __shfl_sync(0xffffffffu, aw, t + 3);
            float N0 = __shfl_sync(0xffffffffu, nsv, t);
            float N1 = __shfl_sync(0xffffffffu, nsv, t + 1);
            float N2 = __shfl_sync(0xffffffffu, nsv, t + 2);
            float N3 = __shfl_sync(0xffffffffu, nsv, t + 3);
            float4 u0 = ((const float4*)(x + (size_t)s0 * 128))[lane];
            float4 u1 = ((const float4*)(x + (size_t)s1 * 128))[lane];
            float4 u2 = ((const float4*)(x + (size_t)s2 * 128))[lane];
            float4 u3 = ((const float4*)(x + (size_t)s3 * 128))[lane];
            fs.x += u0.x + u1.x + u2.x + u3.x;
            fs.y += u0.y + u1.y + u2.y + u3.y;
            fs.z += u0.z + u1.z + u2.z + u3.z;
            fs.w += u0.w + u1.w + u2.w + u3.w;
            fg.x = fmaf(N0, u0.x, fmaf(N1, u1.x, fmaf(N2, u2.x, fmaf(N3, u3.x, fg.x))));
            fg.y = fmaf(N0, u0.y, fmaf(N1, u1.y, fmaf(N2, u2.y, fmaf(N3, u3.y, fg.y))));
            fg.z = fmaf(N0, u0.z, fmaf(N1, u1.z, fmaf(N2, u2.z, fmaf(N3, u3.z, fg.z))));
            fg.w = fmaf(N0, u0.w, fmaf(N1, u1.w, fmaf(N2, u2.w, fmaf(N3, u3.w, fg.w))));
            fa.x = fmaf(A0, u0.x, fmaf(A1, u1.x, fmaf(A2, u2.x, fmaf(A3, u3.x, fa.x))));
            fa.y = fmaf(A0, u0.y, fmaf(A1, u1.y, fmaf(A2, u2.y, fmaf(A3, u3.y, fa.y))));
            fa.z = fmaf(A0, u0.z, fmaf(A1, u1.z, fmaf(A2, u2.z, fmaf(A3, u3.z, fa.z))));
            fa.w = fmaf(A0, u0.w, fmaf(A1, u1.w, fmaf(A2, u2.w, fmaf(A3, u3.w, fa.w))));
        }
        for (; t < cnt; t++) {
            int sv = __shfl_sync(0xffffffffu, sj, t);
            float a = __shfl_sync(0xffffffffu, aw, t);
            float nv = __shfl_sync(0xffffffffu, nsv, t);
            float4 u = ((const float4*)(x + (size_t)sv * 128))[lane];
            fs.x += u.x; fs.y += u.y; fs.z += u.z; fs.w += u.w;
            fg.x = fmaf(nv, u.x, fg.x); fg.y = fmaf(nv, u.y, fg.y);
            fg.z = fmaf(nv, u.z, fg.z); fg.w = fmaf(nv, u.w, fg.w);
            fa.x = fmaf(a, u.x, fa.x); fa.y = fmaf(a, u.y, fa.y);
            fa.z = fmaf(a, u.z, fa.z); fa.w = fmaf(a, u.w, fa.w);
        }
    }
    ss = warp_sum(ss);
    float invd = g_invd[w], ndv = g_nd[w];
    float invs = 1.f / fmaxf(ss, 1e-9f);
    float4* row = (float4*)(g_A + (size_t)w * 512);
    float4 self = ((const float4*)(x + (size_t)w * 128))[lane];
    row[lane] = self;
    row[32 + lane] = make_float4(fs.x * invd, fs.y * invd, fs.z * invd, fs.w * invd);
    row[64 + lane] = make_float4(fg.x * ndv, fg.y * ndv, fg.z * ndv, fg.w * ndv);
    row[96 + lane] = make_float4(fa.x * invs, fa.y * invs, fa.z * invs, fa.w * invs);
}

// ---------------- tf32 tensor-core GEMM (R4 core, templated n-coverage) ----------------
// C[M][Ncols] = A[M][KDIM] @ Bt[Ncols][KDIM]^T
// Block tile: 128 rows x (2*NJ*8) cols; 8 warps as 4m x 2n; per warp 32 rows x NJ*8 cols.
template <int KDIM, int NJ, bool TRANS, bool BIAS>
__global__ __launch_bounds__(256) void gemm_tf32k(
    const float* __restrict__ A, const uint32_t* __restrict__ Bt,
    float* __restrict__ C, int M, int Ncols) {
    constexpr int ROWS_B = 2 * NJ * 8;
    __shared__ uint32_t As[128][20];
    __shared__ uint32_t Bs[ROWS_B][20];
    __shared__ float s_sc[128], s_sh[128], s_b[128];
    int tid = threadIdx.x;
    if (TRANS && tid < 128) { s_sc[tid] = g_bnsc[tid]; s_sh[tid] = g_bnsh[tid]; }
    if (BIAS && tid < 128) s_b[tid] = g_bias1[tid];
    if (TRANS || BIAS) __syncthreads();

    int m0 = blockIdx.x * 128;
    int wid = tid >> 5, lane = tid & 31;
    int mw = (wid & 3) * 32, nw = (wid >> 2) * (NJ * 8);
    int qr = lane >> 2, qc = lane & 3;
    float acc[2][NJ][4];
    #pragma unroll
    for (int mi = 0; mi < 2; mi++)
        #pragma unroll
        for (int nj = 0; nj < NJ; nj++)
            #pragma unroll
            for (int q = 0; q < 4; q++) acc[mi][nj][q] = 0.f;

    int lr = tid >> 1;            // 0..127
    int lk = (tid & 1) * 8;       // 0 or 8

    for (int kk = 0; kk < KDIM; kk += 16) {
        // A panel
        {
            int grow = m0 + lr;
            float4 v0 = make_float4(0, 0, 0, 0), v1 = v0;
            if (grow < M) {
                const float* ap = A + (size_t)grow * KDIM + kk + lk;
                v0 = *(const float4*)ap;
                v1 = *(const float4*)(ap + 4);
            }
            if (TRANS) {
                int kb = kk + lk;
                v0.x = fmaxf(fmaf(v0.x, s_sc[kb + 0], s_sh[kb + 0]), 0.f);
                v0.y = fmaxf(fmaf(v0.y, s_sc[kb + 1], s_sh[kb + 1]), 0.f);
                v0.z = fmaxf(fmaf(v0.z, s_sc[kb + 2], s_sh[kb + 2]), 0.f);
                v0.w = fmaxf(fmaf(v0.w, s_sc[kb + 3], s_sh[kb + 3]), 0.f);
                v1.x = fmaxf(fmaf(v1.x, s_sc[kb + 4], s_sh[kb + 4]), 0.f);
                v1.y = fmaxf(fmaf(v1.y, s_sc[kb + 5], s_sh[kb + 5]), 0.f);
                v1.z = fmaxf(fmaf(v1.z, s_sc[kb + 6], s_sh[kb + 6]), 0.f);
                v1.w = fmaxf(fmaf(v1.w, s_sc[kb + 7], s_sh[kb + 7]), 0.f);
            }
            As[lr][lk + 0] = f2tf32(v0.x); As[lr][lk + 1] = f2tf32(v0.y);
            As[lr][lk + 2] = f2tf32(v0.z); As[lr][lk + 3] = f2tf32(v0.w);
            As[lr][lk + 4] = f2tf32(v1.x); As[lr][lk + 5] = f2tf32(v1.y);
            As[lr][lk + 6] = f2tf32(v1.z); As[lr][lk + 7] = f2tf32(v1.w);
        }
        // B panel (ROWS_B rows; already tf32)
        #pragma unroll
        for (int r = lr; r < ROWS_B; r += 128) {
            uint4 v0 = make_uint4(0, 0, 0, 0), v1 = v0;
            if (r < Ncols) {
                const uint32_t* bp = Bt + (size_t)r * KDIM + kk + lk;
                v0 = *(const uint4*)bp;
                v1 = *(const uint4*)(bp + 4);
            }
            Bs[r][lk + 0] = v0.x; Bs[r][lk + 1] = v0.y;
            Bs[r][lk + 2] = v0.z; Bs[r][lk + 3] = v0.w;
            Bs[r][lk + 4] = v1.x; Bs[r][lk + 5] = v1.y;
            Bs[r][lk + 6] = v1.z; Bs[r][lk + 7] = v1.w;
        }
        __syncthreads();
        #pragma unroll
        for (int k0 = 0; k0 < 16; k0 += 8) {
            uint32_t af[2][4];
            #pragma unroll
            for (int mi = 0; mi < 2; mi++) {
                int rb = mw + mi * 16;
                af[mi][0] = As[rb + qr][k0 + qc];
                af[mi][1] = As[rb + 8 + qr][k0 + qc];
                af[mi][2] = As[rb + qr][k0 + 4 + qc];
                af[mi][3] = As[rb + 8 + qr][k0 + 4 + qc];
            }
            uint32_t bf[NJ][2];
            #pragma unroll
            for (int nj = 0; nj < NJ; nj++) {
                int nb = nw + nj * 8;
                bf[nj][0] = Bs[nb + qr][k0 + qc];
                bf[nj][1] = Bs[nb + qr][k0 + 4 + qc];
            }
            #pragma unroll
            for (int mi = 0; mi < 2; mi++)
                #pragma unroll
                for (int nj = 0; nj < NJ; nj++)
                    mma_tf32(acc[mi][nj], af[mi], bf[nj]);
        }
        __syncthreads();
    }
    // epilogue
    #pragma unroll
    for (int mi = 0; mi < 2; mi++) {
        #pragma unroll
        for (int nj = 0; nj < NJ; nj++) {
            int col = nw + nj * 8 + qc * 2;
            if (col >= Ncols) continue;
            float b0 = 0.f, b1 = 0.f;
            if (BIAS) { b0 = s_b[col]; b1 = s_b[col + 1]; }
            int r0 = m0 + mw + mi * 16 + qr;
            int r1 = r0 + 8;
            if (r0 < M)
                *(float2*)(C + (size_t)r0 * Ncols + col) =
                    make_float2(acc[mi][nj][0] + b0, acc[mi][nj][1] + b1);
            if (r1 < M)
                *(float2*)(C + (size_t)r1 * Ncols + col) =
                    make_float2(acc[mi][nj][2] + b0, acc[mi][nj][3] + b1);
        }
    }
}

// ---------------- BatchNorm statistics + finalize (separate passes; R4 form) ----------------
__global__ void k_bnstats() {
    int t = threadIdx.x;
    float s = 0.f, q = 0.f;
    for (int r = blockIdx.x; r < NV; r += gridDim.x) {
        float h = g_H[(size_t)r * 128 + t];
        s += h;
        q = fmaf(h, h, q);
    }
    atomicAdd(&g_bnsum[t], s);
    atomicAdd(&g_bnsq[t], q);
}

__global__ void k_bnfin(const float* __restrict__ g, const float* __restrict__ be) {
    int t = threadIdx.x;
    if (t < 128) {
        float mean = g_bnsum[t] * (1.f / NV);
        float var = g_bnsq[t] * (1.f / NV) - mean * mean;
        float sc = g[t] * rsqrtf(var + 1e-5f);
        g_bnsc[t] = sc;
        g_bnsh[t] = be[t] - mean * sc;
    }
}

// ---------------- layer-2 epilogue: GAT dots + GCN prescale ----------------
__global__ void k_post2(const float* __restrict__ al, const float* __restrict__ ar) {
    int w = (blockIdx.x * blockDim.x + threadIdx.x) >> 5;
    if (w >= NV) return;
    int lane = threadIdx.x & 31;
    float* row = g_P2 + (size_t)w * 160;
    float el = 0.f, er = 0.f;
    for (int c = lane; c < 40; c += 32) {
        float f = row[120 + c];
        el = fmaf(f, al[c], el);
        er = fmaf(f, ar[c], er);
    }
    el = warp_sum(el);
    er = warp_sum(er);
    if (lane == 0) { g_el2[w] = el; g_er2[w] = er; }
    float nsv = g_ns[w];
    for (int c = lane; c < 40; c += 32) row[80 + c] *= nsv;
}

// ---------------- layer-2 edge aggregation + combine + log_softmax ----------------
__global__ void k_agg2(const float* __restrict__ b21, const float* __restrict__ b22,
                       const float* __restrict__ b23, float* __restrict__ out) {
    int w = (blockIdx.x * blockDim.x + threadIdx.x) >> 5;
    if (w >= NV) return;
    int lane = threadIdx.x & 31;
    int s = (w > 0) ? g_rowofs[w - 1] : 0;
    int e = g_rowofs[w];
    float erv = g_er2[w];
    float mx = -1e30f;
    for (int j = s + lane; j < e; j += 32) mx = fmaxf(mx, g_el2[g_srcs[j]]);
    mx = warp_max(mx);
    float me = lrelu(mx + erv);

    float4 acc = make_float4(0, 0, 0, 0);
    float ss = 0.f;
    bool vec = (lane < 30);
    float gatsel = (lane >= 20 && lane < 30) ? 1.f : 0.f;
    for (int base = s; base < e; base += 32) {
        int j = base + lane;
        int sj = 0;
        float aw = 0.f;
        if (j < e) {
            sj = g_srcs[j];
            aw = __expf(lrelu(g_el2[sj] + erv) - me);
            ss += aw;
        }
        int cnt = min(32, e - base);
        int t = 0;
        for (; t + 4 <= cnt; t += 4) {
            int s0 = __shfl_sync(0xffffffffu, sj, t);
            int s1 = __shfl_sync(0xffffffffu, sj, t + 1);
            int s2 = __shfl_sync(0xffffffffu, sj, t + 2);
            int s3 = __shfl_sync(0xffffffffu, sj, t + 3);
            float A0 = __shfl_sync(0xffffffffu, aw, t);
            float A1 = __shfl_sync(0xffffffffu, aw, t + 1);
            float A2 = __shfl_sync(0xffffffffu, aw, t + 2);
            float A3 = __shfl_sync(0xffffffffu, aw, t + 3);
            if (vec) {
                float m0 = gatsel ? A0 : 1.f;
                float m1 = gatsel ? A1 : 1.f;
                float m2 = gatsel ? A2 : 1.f;
                float m3 = gatsel ? A3 : 1.f;
                float4 u0 = ((const float4*)(g_P2 + (size_t)s0 * 160))[10 + lane];
                float4 u1 = ((const float4*)(g_P2 + (size_t)s1 * 160))[10 + lane];
                float4 u2 = ((const float4*)(g_P2 + (size_t)s2 * 160))[10 + lane];
                float4 u3 = ((const float4*)(g_P2 + (size_t)s3 * 160))[10 + lane];
                acc.x = fmaf(m0, u0.x, fmaf(m1, u1.x, fmaf(m2, u2.x, fmaf(m3, u3.x, acc.x))));
                acc.y = fmaf(m0, u0.y, fmaf(m1, u1.y, fmaf(m2, u2.y, fmaf(m3, u3.y, acc.y))));
                acc.z = fmaf(m0, u0.z, fmaf(m1, u1.z, fmaf(m2, u2.z, fmaf(m3, u3.z, acc.z))));
                acc.w = fmaf(m0, u0.w, fmaf(m1, u1.w, fmaf(m2, u2.w, fmaf(m3, u3.w, acc.w))));
            }
        }
        for (; t < cnt; t++) {
            int sv = __shfl_sync(0xffffffffu, sj, t);
            float a = __shfl_sync(0xffffffffu, aw, t);
            if (vec) {
                float m = gatsel ? a : 1.f;
                float4 u = ((const float4*)(g_P2 + (size_t)sv * 160))[10 + lane];
                acc.x = fmaf(m, u.x, acc.x);
                acc.y = fmaf(m, u.y, acc.y);
                acc.z = fmaf(m, u.z, acc.z);
                acc.w = fmaf(m, u.w, acc.w);
            }
        }
    }
    ss = warp_sum(ss);
    float invd = g_invd[w], ndv = g_nd[w];
    float invs = 1.f / fmaxf(ss, 1e-9f);
    int cs = (lane < 10) ? lane : 0;
    float4 sg = shfl4(acc, cs);
    float4 gc = shfl4(acc, cs + 10);
    float4 ga = shfl4(acc, cs + 20);
    float w0 = g_w2[0], w1 = g_w2[1], w2 = g_w2[2];
    float4 val = make_float4(0, 0, 0, 0);
    float lm = -1e30f;
    if (lane < 10) {
        float4 self = ((const float4*)(g_P2 + (size_t)w * 160))[lane];
        float4 bs = ((const float4*)b21)[lane];
        float4 bg = ((const float4*)b22)[lane];
        float4 ba = ((const float4*)b23)[lane];
        val.x = w0 * (self.x + sg.x * invd + bs.x) + w1 * (gc.x * ndv + bg.x) + w2 * (ga.x * invs + ba.x);
        val.y = w0 * (self.y + sg.y * invd + bs.y) + w1 * (gc.y * ndv + bg.y) + w2 * (ga.y * invs + ba.y);
        val.z = w0 * (self.z + sg.z * invd + bs.z) + w1 * (gc.z * ndv + bg.z) + w2 * (ga.z * invs + ba.z);
        val.w = w0 * (self.w + sg.w * invd + bs.w) + w1 * (gc.w * ndv + bg.w) + w2 * (ga.w * invs + ba.w);
        lm = fmaxf(fmaxf(val.x, val.y), fmaxf(val.z, val.w));
    }
    #pragma unroll
    for (int o = 8; o; o >>= 1) lm = fmaxf(lm, __shfl_xor_sync(0xffffffffu, lm, o));
    float se = 0.f;
    if (lane < 10)
        se = __expf(val.x - lm) + __expf(val.y - lm) + __expf(val.z - lm) + __expf(val.w - lm);
    #pragma unroll
    for (int o = 8; o; o >>= 1) se += __shfl_xor_sync(0xffffffffu, se, o);
    float lse = lm + logf(se);
    if (lane < 10) {
        float4 r = make_float4(val.x - lse, val.y - lse, val.z - lse, val.w - lse);
        ((float4*)(out + (size_t)w * 40))[lane] = r;
    }
}

// ---------------- launch ----------------
extern "C" void kernel_launch(void* const* d_in, const int* in_sizes, int n_in,
                              void* d_out, int out_size) {
    const float* x    = (const float*)d_in[0];
    const int*   src  = (const int*)d_in[1];
    const int*   dst  = (const int*)d_in[2];
    const float* w11s = (const float*)d_in[3];
    const float* w11n = (const float*)d_in[4];
    const float* b11  = (const float*)d_in[5];
    const float* w12  = (const float*)d_in[6];
    const float* b12  = (const float*)d_in[7];
    const float* w13  = (const float*)d_in[8];
    const float* a13l = (const float*)d_in[9];
    const float* a13r = (const float*)d_in[10];
    const float* b13  = (const float*)d_in[11];
    const float* cw1  = (const float*)d_in[12];
    const float* g    = (const float*)d_in[13];
    const float* be   = (const float*)d_in[14];
    const float* w21s = (const float*)d_in[15];
    const float* w21n = (const float*)d_in[16];
    const float* b21  = (const float*)d_in[17];
    const float* w22  = (const float*)d_in[18];
    const float* b22  = (const float*)d_in[19];
    const float* w23  = (const float*)d_in[20];
    const float* a23l = (const float*)d_in[21];
    const float* a23r = (const float*)d_in[22];
    const float* b23  = (const float*)d_in[23];
    const float* cw2  = (const float*)d_in[24];
    float* out = (float*)d_out;

    float* dA;  cudaGetSymbolAddress((void**)&dA,  g_A);
    float* dH;  cudaGetSymbolAddress((void**)&dH,  g_H);
    float* dP2; cudaGetSymbolAddress((void**)&dP2, g_P2);
    uint32_t* dW1; cudaGetSymbolAddress((void**)&dW1, g_W1t);
    uint32_t* dW2; cudaGetSymbolAddress((void**)&dW2, g_W2t);

    const int TPB = 256;
    int nblkV = (NV + TPB - 1) / TPB;
    int nblkE = (NE + TPB - 1) / TPB;
    int nblkW = (NV + 7) / 8;  // one warp per node
    int nblkP = (65536 + 20480 + 128 + TPB - 1) / TPB;

    k_zero<<<nblkV, TPB>>>(cw1, cw2);
    k_deg<<<nblkE, TPB>>>(src, dst);
    k_scan<<<1, 1024>>>();
    k_scatter<<<nblkE, TPB>>>(src, dst);
    k_wprep<<<nblkP, TPB>>>(w11s, w11n, w12, w13, b11, b12, b13,
                            w21s, w21n, w22, w23, a13l, a13r);

    k_eler1<<<nblkW, TPB>>>(x);
    k_edge1<<<nblkW, TPB>>>(x);
    gemm_tf32k<512, 8, false, true><<<dim3((NV + 127) / 128, 1), 256>>>(dA, dW1, dH, NV, 128);

    k_bnstats<<<512, 128>>>();
    k_bnfin<<<1, 128>>>(g, be);

    gemm_tf32k<128, 10, true, false><<<dim3((NV + 127) / 128, 1), 256>>>(dH, dW2, dP2, NV, 160);
    k_post2<<<nblkW, TPB>>>(a23l, a23r);
    k_agg2<<<nblkW, TPB>>>(b21, b22, b23, out);
}

// round 13
// speedup vs baseline: 1.2089x; 1.2089x over previous
#include <cuda_runtime.h>
#include <cstdint>

#define NV 50000
#define NE 1600000

// ---------------- scratch ----------------
__device__ __align__(16) float g_A[NV * 512];        // [x | sage | gcn | gat] layer1 GEMM input
__device__ __align__(16) float g_H[NV * 128];        // layer1 output (pre-BN)
__device__ __align__(16) float g_P2[NV * 160];       // layer2 GEMM output [self|sage|gcn|gat]
__device__ __align__(16) uint32_t g_W1t[128 * 512];  // tf32, [n][k]
__device__ __align__(16) uint32_t g_W2t[160 * 128];  // tf32, [n][k]
__device__ float g_bias1[128];
__device__ int g_indeg[NV];
__device__ int g_outdeg[NV];
__device__ int g_cursor[NV];
__device__ int g_rowofs[NV + 1];
__device__ int g_srcs[NE];
__device__ float g_ns[NV], g_nd[NV], g_invd[NV];
__device__ float g_el1[NV], g_er1[NV], g_el2[NV], g_er2[NV];
__device__ float g_wl1[128], g_wr1[128];
__device__ float g_bnsum[128], g_bnsq[128], g_bnsc[128], g_bnsh[128];
__device__ float g_w1[3], g_w2[3];

// ---------------- helpers ----------------
__device__ __forceinline__ float lrelu(float x) { return x > 0.f ? x : 0.2f * x; }
__device__ __forceinline__ float warp_max(float v) {
    #pragma unroll
    for (int o = 16; o; o >>= 1) v = fmaxf(v, __shfl_xor_sync(0xffffffffu, v, o));
    return v;
}
__device__ __forceinline__ float warp_sum(float v) {
    #pragma unroll
    for (int o = 16; o; o >>= 1) v += __shfl_xor_sync(0xffffffffu, v, o);
    return v;
}
__device__ __forceinline__ float4 shfl4(float4 v, int src) {
    float4 r;
    r.x = __shfl_sync(0xffffffffu, v.x, src);
    r.y = __shfl_sync(0xffffffffu, v.y, src);
    r.z = __shfl_sync(0xffffffffu, v.z, src);
    r.w = __shfl_sync(0xffffffffu, v.w, src);
    return r;
}
__device__ __forceinline__ uint32_t f2tf32(float v) {
    uint32_t r;
    asm("cvt.rna.tf32.f32 %0, %1;" : "=r"(r) : "f"(v));
    return r;
}
__device__ __forceinline__ void mma_tf32(float c[4], const uint32_t a[4], const uint32_t b[2]) {
    asm volatile(
        "mma.sync.aligned.m16n8k8.row.col.f32.tf32.tf32.f32 "
        "{%0,%1,%2,%3}, {%4,%5,%6,%7}, {%8,%9}, {%0,%1,%2,%3};"
        : "+f"(c[0]), "+f"(c[1]), "+f"(c[2]), "+f"(c[3])
        : "r"(a[0]), "r"(a[1]), "r"(a[2]), "r"(a[3]), "r"(b[0]), "r"(b[1]));
}

// ---------------- setup ----------------
__global__ void k_zero(const float* __restrict__ cw1, const float* __restrict__ cw2) {
    int i = blockIdx.x * blockDim.x + threadIdx.x;
    if (i < NV) { g_indeg[i] = 0; g_outdeg[i] = 0; g_cursor[i] = 0; }
    if (i < 128) { g_bnsum[i] = 0.f; g_bnsq[i] = 0.f; }
    if (i == 0) {
        float s1 = cw1[0] + cw1[1] + cw1[2];
        g_w1[0] = cw1[0] / s1; g_w1[1] = cw1[1] / s1; g_w1[2] = cw1[2] / s1;
        float s2 = cw2[0] + cw2[1] + cw2[2];
        g_w2[0] = cw2[0] / s2; g_w2[1] = cw2[1] / s2; g_w2[2] = cw2[2] / s2;
    }
}

__global__ void k_deg(const int* __restrict__ src, const int* __restrict__ dst) {
    int i = blockIdx.x * blockDim.x + threadIdx.x;
    if (i < NE) {
        atomicAdd(&g_indeg[dst[i]], 1);
        atomicAdd(&g_outdeg[src[i]], 1);
    }
}

// single-pass scan: 1024 threads, each owns a contiguous chunk
__global__ void k_scan() {
    int t = threadIdx.x;
    const int CH = (NV + 1023) / 1024;
    int b0 = t * CH;
    int b1 = min(b0 + CH, NV);
    int sum = 0;
    for (int i = b0; i < b1; i++) sum += g_indeg[i];
    __shared__ int wsum[32];
    int lane = t & 31, wid = t >> 5;
    int v = sum;
    #pragma unroll
    for (int o = 1; o < 32; o <<= 1) {
        int u = __shfl_up_sync(0xffffffffu, v, o);
        if (lane >= o) v += u;
    }
    if (lane == 31) wsum[wid] = v;
    __syncthreads();
    if (wid == 0) {
        int wv = wsum[lane];
        #pragma unroll
        for (int o = 1; o < 32; o <<= 1) {
            int u = __shfl_up_sync(0xffffffffu, wv, o);
            if (lane >= o) wv += u;
        }
        wsum[lane] = wv;
    }
    __syncthreads();
    int excl = v - sum + (wid > 0 ? wsum[wid - 1] : 0);
    int run = excl;
    for (int i = b0; i < b1; i++) { g_rowofs[i] = run; run += g_indeg[i]; }
    if (t == 1023) g_rowofs[NV] = run;
}

__global__ void k_nodefac() {
    int i = blockIdx.x * blockDim.x + threadIdx.x;
    if (i < NV) {
        float di = fmaxf((float)g_indeg[i], 1.f);
        float doo = fmaxf((float)g_outdeg[i], 1.f);
        g_nd[i] = rsqrtf(di);
        g_ns[i] = rsqrtf(doo);
        g_invd[i] = 1.f / di;
    }
}

__global__ void k_scatter(const int* __restrict__ src, const int* __restrict__ dst) {
    int i = blockIdx.x * blockDim.x + threadIdx.x;
    if (i < NE) {
        int d = dst[i];
        int pos = g_rowofs[d] + atomicAdd(&g_cursor[d], 1);
        g_srcs[pos] = src[i];
    }
}

// W1t[n][k] = scaled, tf32-converted, transposed combined weight (K=512)
__global__ void k_copyW1(const float* __restrict__ ws, const float* __restrict__ wn,
                         const float* __restrict__ wg, const float* __restrict__ wa,
                         const float* __restrict__ b11, const float* __restrict__ b12,
                         const float* __restrict__ b13) {
    int i = blockIdx.x * blockDim.x + threadIdx.x;
    if (i < 128 * 512) {
        int c = i >> 9, k = i & 511;
        float v;
        if (k < 128)      v = g_w1[0] * ws[k * 128 + c];
        else if (k < 256) v = g_w1[0] * wn[(k - 128) * 128 + c];
        else if (k < 384) v = g_w1[1] * wg[(k - 256) * 128 + c];
        else              v = g_w1[2] * wa[(k - 384) * 128 + c];
        g_W1t[i] = f2tf32(v);
    }
    if (i < 128)
        g_bias1[i] = g_w1[0] * b11[i] + g_w1[1] * b12[i] + g_w1[2] * b13[i];
}

// W2t[n][k], n in blocks [self|sage|gcn|gat] of 40
__global__ void k_copyW2(const float* __restrict__ ws, const float* __restrict__ wn,
                         const float* __restrict__ wg, const float* __restrict__ wa) {
    int i = blockIdx.x * blockDim.x + threadIdx.x;
    if (i < 160 * 128) {
        int c = i >> 7, k = i & 127;
        float v;
        if (c < 40)       v = ws[k * 40 + c];
        else if (c < 80)  v = wn[k * 40 + (c - 40)];
        else if (c < 120) v = wg[k * 40 + (c - 80)];
        else              v = wa[k * 40 + (c - 120)];
        g_W2t[i] = f2tf32(v);
    }
}

// attention projection vectors: wl = W13 @ a13l, wr = W13 @ a13r
__global__ void k_wvec(const float* __restrict__ w13, const float* __restrict__ al,
                       const float* __restrict__ ar) {
    int k = threadIdx.x;
    float sl = 0.f, sr = 0.f;
    for (int j = 0; j < 128; j++) {
        float w = w13[k * 128 + j];
        sl = fmaf(w, al[j], sl);
        sr = fmaf(w, ar[j], sr);
    }
    g_wl1[k] = sl;
    g_wr1[k] = sr;
}

// per-node attention scalars for layer 1
__global__ void k_eler1(const float* __restrict__ x) {
    int w = (blockIdx.x * blockDim.x + threadIdx.x) >> 5;
    if (w >= NV) return;
    int lane = threadIdx.x & 31;
    float4 u = ((const float4*)(x + (size_t)w * 128))[lane];
    float4 wl = ((const float4*)g_wl1)[lane];
    float4 wr = ((const float4*)g_wr1)[lane];
    float el = u.x * wl.x + u.y * wl.y + u.z * wl.z + u.w * wl.w;
    float er = u.x * wr.x + u.y * wr.y + u.z * wr.z + u.w * wr.w;
    el = warp_sum(el);
    er = warp_sum(er);
    if (lane == 0) { g_el1[w] = el; g_er1[w] = er; }
}

// layer-1 edge pass: gather x[src], 4-edge unrolled (MLP=4)
__global__ void k_edge1(const float* __restrict__ x) {
    int w = (blockIdx.x * blockDim.x + threadIdx.x) >> 5;
    if (w >= NV) return;
    int lane = threadIdx.x & 31;
    int s = g_rowofs[w], e = g_rowofs[w + 1];
    float erv = g_er1[w];
    float mx = -1e30f;
    for (int j = s + lane; j < e; j += 32) mx = fmaxf(mx, g_el1[g_srcs[j]]);
    mx = warp_max(mx);
    float me = lrelu(mx + erv);

    float4 fs = make_float4(0, 0, 0, 0), fg = fs, fa = fs;
    float ss = 0.f;
    for (int base = s; base < e; base += 32) {
        int j = base + lane;
        int sj = 0;
        float aw = 0.f, nsv = 0.f;
        if (j < e) {
            sj = g_srcs[j];
            aw = __expf(lrelu(g_el1[sj] + erv) - me);
            nsv = g_ns[sj];
            ss += aw;
        }
        int cnt = min(32, e - base);
        int t = 0;
        for (; t + 4 <= cnt; t += 4) {
            int s0 = __shfl_sync(0xffffffffu, sj, t);
            int s1 = __shfl_sync(0xffffffffu, sj, t + 1);
            int s2 = __shfl_sync(0xffffffffu, sj, t + 2);
            int s3 = __shfl_sync(0xffffffffu, sj, t + 3);
            float A0 = __shfl_sync(0xffffffffu, aw, t);
            float A1 = __shfl_sync(0xffffffffu, aw, t + 1);
            float A2 = __shfl_sync(0xffffffffu, aw, t + 2);
            float A3 = __shfl_sync(0xffffffffu, aw, t + 3);
            float N0 = __shfl_sync(0xffffffffu, nsv, t);
            float N1 = __shfl_sync(0xffffffffu, nsv, t + 1);
            float N2 = __shfl_sync(0xffffffffu, nsv, t + 2);
            float N3 = __shfl_sync(0xffffffffu, nsv, t + 3);
            float4 u0 = ((const float4*)(x + (size_t)s0 * 128))[lane];
            float4 u1 = ((const float4*)(x + (size_t)s1 * 128))[lane];
            float4 u2 = ((const float4*)(x + (size_t)s2 * 128))[lane];
            float4 u3 = ((const float4*)(x + (size_t)s3 * 128))[lane];
            fs.x += u0.x + u1.x + u2.x + u3.x;
            fs.y += u0.y + u1.y + u2.y + u3.y;
            fs.z += u0.z + u1.z + u2.z + u3.z;
            fs.w += u0.w + u1.w + u2.w + u3.w;
            fg.x = fmaf(N0, u0.x, fmaf(N1, u1.x, fmaf(N2, u2.x, fmaf(N3, u3.x, fg.x))));
            fg.y = fmaf(N0, u0.y, fmaf(N1, u1.y, fmaf(N2, u2.y, fmaf(N3, u3.y, fg.y))));
            fg.z = fmaf(N0, u0.z, fmaf(N1, u1.z, fmaf(N2, u2.z, fmaf(N3, u3.z, fg.z))));
            fg.w = fmaf(N0, u0.w, fmaf(N1, u1.w, fmaf(N2, u2.w, fmaf(N3, u3.w, fg.w))));
            fa.x = fmaf(A0, u0.x, fmaf(A1, u1.x, fmaf(A2, u2.x, fmaf(A3, u3.x, fa.x))));
            fa.y = fmaf(A0, u0.y, fmaf(A1, u1.y, fmaf(A2, u2.y, fmaf(A3, u3.y, fa.y))));
            fa.z = fmaf(A0, u0.z, fmaf(A1, u1.z, fmaf(A2, u2.z, fmaf(A3, u3.z, fa.z))));
            fa.w = fmaf(A0, u0.w, fmaf(A1, u1.w, fmaf(A2, u2.w, fmaf(A3, u3.w, fa.w))));
        }
        for (; t < cnt; t++) {
            int sv = __shfl_sync(0xffffffffu, sj, t);
            float a = __shfl_sync(0xffffffffu, aw, t);
            float nv = __shfl_sync(0xffffffffu, nsv, t);
            float4 u = ((const float4*)(x + (size_t)sv * 128))[lane];
            fs.x += u.x; fs.y += u.y; fs.z += u.z; fs.w += u.w;
            fg.x = fmaf(nv, u.x, fg.x); fg.y = fmaf(nv, u.y, fg.y);
            fg.z = fmaf(nv, u.z, fg.z); fg.w = fmaf(nv, u.w, fg.w);
            fa.x = fmaf(a, u.x, fa.x); fa.y = fmaf(a, u.y, fa.y);
            fa.z = fmaf(a, u.z, fa.z); fa.w = fmaf(a, u.w, fa.w);
        }
    }
    ss = warp_sum(ss);
    float invd = g_invd[w], ndv = g_nd[w];
    float invs = 1.f / fmaxf(ss, 1e-9f);
    float4* row = (float4*)(g_A + (size_t)w * 512);
    float4 self = ((const float4*)(x + (size_t)w * 128))[lane];
    row[lane] = self;
    row[32 + lane] = make_float4(fs.x * invd, fs.y * invd, fs.z * invd, fs.w * invd);
    row[64 + lane] = make_float4(fg.x * ndv, fg.y * ndv, fg.z * ndv, fg.w * ndv);
    row[96 + lane] = make_float4(fa.x * invs, fa.y * invs, fa.z * invs, fa.w * invs);
}

// ---------------- tf32 tensor-core GEMM ----------------
// C[M][Ncols] = A[M][KDIM] @ Bt[Ncols][KDIM]^T ; 128x128 tile, 8 warps (4m x 2n)
template <int KDIM, bool TRANS, bool BIAS>
__global__ __launch_bounds__(256) void gemm_tf32(
    const float* __restrict__ A, const uint32_t* __restrict__ Bt,
    float* __restrict__ C, int M, int Ncols) {
    __shared__ uint32_t As[128][20];
    __shared__ uint32_t Bs[128][20];
    __shared__ float s_sc[128], s_sh[128], s_b[128];
    int tid = threadIdx.x;
    if (TRANS && tid < 128) { s_sc[tid] = g_bnsc[tid]; s_sh[tid] = g_bnsh[tid]; }
    if (BIAS && tid < 128) s_b[tid] = g_bias1[tid];
    if (TRANS || BIAS) __syncthreads();

    int m0 = blockIdx.x * 128, n0 = blockIdx.y * 128;
    int wid = tid >> 5, lane = tid & 31;
    int mw = (wid & 3) * 32, nw = (wid >> 2) * 64;
    int qr = lane >> 2, qc = lane & 3;
    float acc[2][8][4];
    #pragma unroll
    for (int mi = 0; mi < 2; mi++)
        #pragma unroll
        for (int nj = 0; nj < 8; nj++)
            #pragma unroll
            for (int q = 0; q < 4; q++) acc[mi][nj][q] = 0.f;

    int lr = tid >> 1;            // 0..127
    int lk = (tid & 1) * 8;       // 0 or 8

    for (int kk = 0; kk < KDIM; kk += 16) {
        // A panel: rows m0+lr, k = kk+lk .. +7
        {
            int grow = m0 + lr;
            float4 v0 = make_float4(0, 0, 0, 0), v1 = v0;
            if (grow < M) {
                const float* ap = A + (size_t)grow * KDIM + kk + lk;
                v0 = *(const float4*)ap;
                v1 = *(const float4*)(ap + 4);
            }
            if (TRANS) {
                int kb = kk + lk;
                v0.x = fmaxf(fmaf(v0.x, s_sc[kb + 0], s_sh[kb + 0]), 0.f);
                v0.y = fmaxf(fmaf(v0.y, s_sc[kb + 1], s_sh[kb + 1]), 0.f);
                v0.z = fmaxf(fmaf(v0.z, s_sc[kb + 2], s_sh[kb + 2]), 0.f);
                v0.w = fmaxf(fmaf(v0.w, s_sc[kb + 3], s_sh[kb + 3]), 0.f);
                v1.x = fmaxf(fmaf(v1.x, s_sc[kb + 4], s_sh[kb + 4]), 0.f);
                v1.y = fmaxf(fmaf(v1.y, s_sc[kb + 5], s_sh[kb + 5]), 0.f);
                v1.z = fmaxf(fmaf(v1.z, s_sc[kb + 6], s_sh[kb + 6]), 0.f);
                v1.w = fmaxf(fmaf(v1.w, s_sc[kb + 7], s_sh[kb + 7]), 0.f);
            }
            As[lr][lk + 0] = f2tf32(v0.x); As[lr][lk + 1] = f2tf32(v0.y);
            As[lr][lk + 2] = f2tf32(v0.z); As[lr][lk + 3] = f2tf32(v0.w);
            As[lr][lk + 4] = f2tf32(v1.x); As[lr][lk + 5] = f2tf32(v1.y);
            As[lr][lk + 6] = f2tf32(v1.z); As[lr][lk + 7] = f2tf32(v1.w);
        }
        // B panel: n = n0+lr, k = kk+lk .. +7 (already tf32)
        {
            int gn = n0 + lr;
            uint4 v0 = make_uint4(0, 0, 0, 0), v1 = v0;
            if (gn < Ncols) {
                const uint32_t* bp = Bt + (size_t)gn * KDIM + kk + lk;
                v0 = *(const uint4*)bp;
                v1 = *(const uint4*)(bp + 4);
            }
            Bs[lr][lk + 0] = v0.x; Bs[lr][lk + 1] = v0.y;
            Bs[lr][lk + 2] = v0.z; Bs[lr][lk + 3] = v0.w;
            Bs[lr][lk + 4] = v1.x; Bs[lr][lk + 5] = v1.y;
            Bs[lr][lk + 6] = v1.z; Bs[lr][lk + 7] = v1.w;
        }
        __syncthreads();
        #pragma unroll
        for (int k0 = 0; k0 < 16; k0 += 8) {
            uint32_t af[2][4];
            #pragma unroll
            for (int mi = 0; mi < 2; mi++) {
                int rb = mw + mi * 16;
                af[mi][0] = As[rb + qr][k0 + qc];
                af[mi][1] = As[rb + 8 + qr][k0 + qc];
                af[mi][2] = As[rb + qr][k0 + 4 + qc];
                af[mi][3] = As[rb + 8 + qr][k0 + 4 + qc];
            }
            uint32_t bf[8][2];
            #pragma unroll
            for (int nj = 0; nj < 8; nj++) {
                int nb = nw + nj * 8;
                bf[nj][0] = Bs[nb + qr][k0 + qc];
                bf[nj][1] = Bs[nb + qr][k0 + 4 + qc];
            }
            #pragma unroll
            for (int mi = 0; mi < 2; mi++)
                #pragma unroll
                for (int nj = 0; nj < 8; nj++)
                    mma_tf32(acc[mi][nj], af[mi], bf[nj]);
        }
        __syncthreads();
    }
    // epilogue
    #pragma unroll
    for (int mi = 0; mi < 2; mi++) {
        #pragma unroll
        for (int nj = 0; nj < 8; nj++) {
            int col = n0 + nw + nj * 8 + qc * 2;
            if (col + 1 >= Ncols && col >= Ncols) continue;
            float b0 = 0.f, b1 = 0.f;
            if (BIAS) { b0 = s_b[col - n0]; b1 = s_b[col - n0 + 1]; }
            int r0 = m0 + mw + mi * 16 + qr;
            int r1 = r0 + 8;
            if (r0 < M && col + 1 < Ncols) {
                float2 v = make_float2(acc[mi][nj][0] + b0, acc[mi][nj][1] + b1);
                *(float2*)(C + (size_t)r0 * Ncols + col) = v;
            }
            if (r1 < M && col + 1 < Ncols) {
                float2 v = make_float2(acc[mi][nj][2] + b0, acc[mi][nj][3] + b1);
                *(float2*)(C + (size_t)r1 * Ncols + col) = v;
            }
        }
    }
}

// ---------------- BatchNorm statistics + finalize ----------------
__global__ void k_bnstats() {
    int t = threadIdx.x;
    float s = 0.f, q = 0.f;
    for (int r = blockIdx.x; r < NV; r += gridDim.x) {
        float h = g_H[(size_t)r * 128 + t];
        s += h;
        q = fmaf(h, h, q);
    }
    atomicAdd(&g_bnsum[t], s);
    atomicAdd(&g_bnsq[t], q);
}

__global__ void k_bnfin(const float* __restrict__ g, const float* __restrict__ be) {
    int t = threadIdx.x;
    if (t < 128) {
        float mean = g_bnsum[t] * (1.f / NV);
        float var = g_bnsq[t] * (1.f / NV) - mean * mean;
        float sc = g[t] * rsqrtf(var + 1e-5f);
        g_bnsc[t] = sc;
        g_bnsh[t] = be[t] - mean * sc;
    }
}

// ---------------- layer-2 epilogue: GAT dots + GCN prescale on P2 ----------------
__global__ void k_post2(const float* __restrict__ al, const float* __restrict__ ar) {
    int w = (blockIdx.x * blockDim.x + threadIdx.x) >> 5;
    if (w >= NV) return;
    int lane = threadIdx.x & 31;
    float* row = g_P2 + (size_t)w * 160;
    float el = 0.f, er = 0.f;
    for (int c = lane; c < 40; c += 32) {
        float f = row[120 + c];
        el = fmaf(f, al[c], el);
        er = fmaf(f, ar[c], er);
    }
    el = warp_sum(el);
    er = warp_sum(er);
    if (lane == 0) { g_el2[w] = el; g_er2[w] = er; }
    float nsv = g_ns[w];
    for (int c = lane; c < 40; c += 32) row[80 + c] *= nsv;
}

// ---------------- layer-2 edge aggregation + combine + log_softmax ----------------
__global__ void k_agg2(const float* __restrict__ b21, const float* __restrict__ b22,
                       const float* __restrict__ b23, float* __restrict__ out) {
    int w = (blockIdx.x * blockDim.x + threadIdx.x) >> 5;
    if (w >= NV) return;
    int lane = threadIdx.x & 31;
    int s = g_rowofs[w], e = g_rowofs[w + 1];
    float erv = g_er2[w];
    float mx = -1e30f;
    for (int j = s + lane; j < e; j += 32) mx = fmaxf(mx, g_el2[g_srcs[j]]);
    mx = warp_max(mx);
    float me = lrelu(mx + erv);

    float4 acc = make_float4(0, 0, 0, 0);
    float ss = 0.f;
    bool vec = (lane < 30);
    float gatsel = (lane >= 20 && lane < 30) ? 1.f : 0.f;
    for (int base = s; base < e; base += 32) {
        int j = base + lane;
        int sj = 0;
        float aw = 0.f;
        if (j < e) {
            sj = g_srcs[j];
            aw = __expf(lrelu(g_el2[sj] + erv) - me);
            ss += aw;
        }
        int cnt = min(32, e - base);
        int t = 0;
        for (; t + 4 <= cnt; t += 4) {
            int s0 = __shfl_sync(0xffffffffu, sj, t);
            int s1 = __shfl_sync(0xffffffffu, sj, t + 1);
            int s2 = __shfl_sync(0xffffffffu, sj, t + 2);
            int s3 = __shfl_sync(0xffffffffu, sj, t + 3);
            float A0 = __shfl_sync(0xffffffffu, aw, t);
            float A1 = __shfl_sync(0xffffffffu, aw, t + 1);
            float A2 = __shfl_sync(0xffffffffu, aw, t + 2);
            float A3 = __shfl_sync(0xffffffffu, aw, t + 3);
            if (vec) {
                float m0 = gatsel ? A0 : 1.f;
                float m1 = gatsel ? A1 : 1.f;
                float m2 = gatsel ? A2 : 1.f;
                float m3 = gatsel ? A3 : 1.f;
                float4 u0 = ((const float4*)(g_P2 + (size_t)s0 * 160))[10 + lane];
                float4 u1 = ((const float4*)(g_P2 + (size_t)s1 * 160))[10 + lane];
                float4 u2 = ((const float4*)(g_P2 + (size_t)s2 * 160))[10 + lane];
                float4 u3 = ((const float4*)(g_P2 + (size_t)s3 * 160))[10 + lane];
                acc.x = fmaf(m0, u0.x, fmaf(m1, u1.x, fmaf(m2, u2.x, fmaf(m3, u3.x, acc.x))));
                acc.y = fmaf(m0, u0.y, fmaf(m1, u1.y, fmaf(m2, u2.y, fmaf(m3, u3.y, acc.y))));
                acc.z = fmaf(m0, u0.z, fmaf(m1, u1.z, fmaf(m2, u2.z, fmaf(m3, u3.z, acc.z))));
                acc.w = fmaf(m0, u0.w, fmaf(m1, u1.w, fmaf(m2, u2.w, fmaf(m3, u3.w, acc.w))));
            }
        }
        for (; t < cnt; t++) {
            int sv = __shfl_sync(0xffffffffu, sj, t);
            float a = __shfl_sync(0xffffffffu, aw, t);
            if (vec) {
                float m = gatsel ? a : 1.f;
                float4 u = ((const float4*)(g_P2 + (size_t)sv * 160))[10 + lane];
                acc.x = fmaf(m, u.x, acc.x);
                acc.y = fmaf(m, u.y, acc.y);
                acc.z = fmaf(m, u.z, acc.z);
                acc.w = fmaf(m, u.w, acc.w);
            }
        }
    }
    ss = warp_sum(ss);
    float invd = g_invd[w], ndv = g_nd[w];
    float invs = 1.f / fmaxf(ss, 1e-9f);
    int cs = (lane < 10) ? lane : 0;
    float4 sg = shfl4(acc, cs);
    float4 gc = shfl4(acc, cs + 10);
    float4 ga = shfl4(acc, cs + 20);
    float w0 = g_w2[0], w1 = g_w2[1], w2 = g_w2[2];
    float4 val = make_float4(0, 0, 0, 0);
    float lm = -1e30f;
    if (lane < 10) {
        float4 self = ((const float4*)(g_P2 + (size_t)w * 160))[lane];
        float4 bs = ((const float4*)b21)[lane];
        float4 bg = ((const float4*)b22)[lane];
        float4 ba = ((const float4*)b23)[lane];
        val.x = w0 * (self.x + sg.x * invd + bs.x) + w1 * (gc.x * ndv + bg.x) + w2 * (ga.x * invs + ba.x);
        val.y = w0 * (self.y + sg.y * invd + bs.y) + w1 * (gc.y * ndv + bg.y) + w2 * (ga.y * invs + ba.y);
        val.z = w0 * (self.z + sg.z * invd + bs.z) + w1 * (gc.z * ndv + bg.z) + w2 * (ga.z * invs + ba.z);
        val.w = w0 * (self.w + sg.w * invd + bs.w) + w1 * (gc.w * ndv + bg.w) + w2 * (ga.w * invs + ba.w);
        lm = fmaxf(fmaxf(val.x, val.y), fmaxf(val.z, val.w));
    }
    #pragma unroll
    for (int o = 8; o; o >>= 1) lm = fmaxf(lm, __shfl_xor_sync(0xffffffffu, lm, o));
    float se = 0.f;
    if (lane < 10)
        se = __expf(val.x - lm) + __expf(val.y - lm) + __expf(val.z - lm) + __expf(val.w - lm);
    #pragma unroll
    for (int o = 8; o; o >>= 1) se += __shfl_xor_sync(0xffffffffu, se, o);
    float lse = lm + logf(se);
    if (lane < 10) {
        float4 r = make_float4(val.x - lse, val.y - lse, val.z - lse, val.w - lse);
        ((float4*)(out + (size_t)w * 40))[lane] = r;
    }
}

// ---------------- launch ----------------
extern "C" void kernel_launch(void* const* d_in, const int* in_sizes, int n_in,
                              void* d_out, int out_size) {
    const float* x    = (const float*)d_in[0];
    const int*   src  = (const int*)d_in[1];
    const int*   dst  = (const int*)d_in[2];
    const float* w11s = (const float*)d_in[3];
    const float* w11n = (const float*)d_in[4];
    const float* b11  = (const float*)d_in[5];
    const float* w12  = (const float*)d_in[6];
    const float* b12  = (const float*)d_in[7];
    const float* w13  = (const float*)d_in[8];
    const float* a13l = (const float*)d_in[9];
    const float* a13r = (const float*)d_in[10];
    const float* b13  = (const float*)d_in[11];
    const float* cw1  = (const float*)d_in[12];
    const float* g    = (const float*)d_in[13];
    const float* be   = (const float*)d_in[14];
    const float* w21s = (const float*)d_in[15];
    const float* w21n = (const float*)d_in[16];
    const float* b21  = (const float*)d_in[17];
    const float* w22  = (const float*)d_in[18];
    const float* b22  = (const float*)d_in[19];
    const float* w23  = (const float*)d_in[20];
    const float* a23l = (const float*)d_in[21];
    const float* a23r = (const float*)d_in[22];
    const float* b23  = (const float*)d_in[23];
    const float* cw2  = (const float*)d_in[24];
    float* out = (float*)d_out;

    float* dA;  cudaGetSymbolAddress((void**)&dA,  g_A);
    float* dH;  cudaGetSymbolAddress((void**)&dH,  g_H);
    float* dP2; cudaGetSymbolAddress((void**)&dP2, g_P2);
    uint32_t* dW1; cudaGetSymbolAddress((void**)&dW1, g_W1t);
    uint32_t* dW2; cudaGetSymbolAddress((void**)&dW2, g_W2t);

    const int TPB = 256;
    int nblkV = (NV + TPB - 1) / TPB;
    int nblkE = (NE + TPB - 1) / TPB;
    int nblkW = (NV + 7) / 8;  // one warp per node

    k_zero<<<nblkV, TPB>>>(cw1, cw2);
    k_deg<<<nblkE, TPB>>>(src, dst);
    k_scan<<<1, 1024>>>();
    k_nodefac<<<nblkV, TPB>>>();
    k_scatter<<<nblkE, TPB>>>(src, dst);
    k_copyW1<<<(128 * 512) / TPB, TPB>>>(w11s, w11n, w12, w13, b11, b12, b13);
    k_copyW2<<<(160 * 128 + TPB - 1) / TPB, TPB>>>(w21s, w21n, w22, w23);
    k_wvec<<<1, 128>>>(w13, a13l, a13r);

    k_eler1<<<nblkW, TPB>>>(x);
    k_edge1<<<nblkW, TPB>>>(x);
    gemm_tf32<512, false, true><<<dim3((NV + 127) / 128, 1), 256>>>(dA, dW1, dH, NV, 128);

    k_bnstats<<<512, 128>>>();
    k_bnfin<<<1, 128>>>(g, be);

    gemm_tf32<128, true, false><<<dim3((NV + 127) / 128, 2), 256>>>(dH, dW2, dP2, NV, 160);
    k_post2<<<nblkW, TPB>>>(a23l, a23r);
    k_agg2<<<nblkW, TPB>>>(b21, b22, b23, out);
}